// round 15
// baseline (speedup 1.0000x reference)
#include <cuda_runtime.h>
#include <cuda_fp16.h>
#include <cstdint>

#define CEXP 0.18033688011112042f   // 0.125 * log2(e), folded into Q projection

// fp16 scratch
static __device__ __align__(16) __half g_xh[8388608];   // x as fp16
static __device__ __align__(16) __half g_wh[4194304];   // wq|wk|wv|wo as fp16
static __device__ __align__(16) __half g_qh[8388608];   // [b][h][s][d], pre-scaled by CEXP
static __device__ __align__(16) __half g_kh[8388608];
static __device__ __align__(16) __half g_vh[8388608];
static __device__ __align__(16) __half g_aoh[8388608];  // [b][s][h*d]

// ---------------------------------------------------------------------------
__device__ __forceinline__ uint32_t smem_u32(const void* p) {
    uint32_t a;
    asm("{ .reg .u64 t; cvta.to.shared.u64 t, %1; cvt.u32.u64 %0, t; }" : "=r"(a) : "l"(p));
    return a;
}
#define CP16(s, g) asm volatile("cp.async.cg.shared.global [%0], [%1], 16;" :: "r"(s), "l"(g))
#define CP_COMMIT() asm volatile("cp.async.commit_group;" ::: "memory")
#define CP_WAIT0()  asm volatile("cp.async.wait_group 0;" ::: "memory")
#define CP_WAIT1()  asm volatile("cp.async.wait_group 1;" ::: "memory")

__device__ __forceinline__ void ldsm4(uint32_t* r, uint32_t a) {
    asm volatile("ldmatrix.sync.aligned.m8n8.x4.shared.b16 {%0,%1,%2,%3}, [%4];"
                 : "=r"(r[0]), "=r"(r[1]), "=r"(r[2]), "=r"(r[3]) : "r"(a));
}
__device__ __forceinline__ void ldsm4t(uint32_t* r, uint32_t a) {
    asm volatile("ldmatrix.sync.aligned.m8n8.x4.trans.shared.b16 {%0,%1,%2,%3}, [%4];"
                 : "=r"(r[0]), "=r"(r[1]), "=r"(r[2]), "=r"(r[3]) : "r"(a));
}
__device__ __forceinline__ void mma16816(float* c, const uint32_t* a, uint32_t b0, uint32_t b1) {
    asm volatile("mma.sync.aligned.m16n8k16.row.col.f32.f16.f16.f32 "
                 "{%0,%1,%2,%3}, {%4,%5,%6,%7}, {%8,%9}, {%0,%1,%2,%3};"
                 : "+f"(c[0]), "+f"(c[1]), "+f"(c[2]), "+f"(c[3])
                 : "r"(a[0]), "r"(a[1]), "r"(a[2]), "r"(a[3]), "r"(b0), "r"(b1));
}
__device__ __forceinline__ uint32_t packh2(float lo, float hi) {
    uint32_t r;
    asm("cvt.rn.f16x2.f32 %0, %1, %2;" : "=r"(r) : "f"(hi), "f"(lo));
    return r;
}
__device__ __forceinline__ uint32_t hmax2(uint32_t a, uint32_t b) {
    uint32_t r;
    asm("max.f16x2 %0, %1, %2;" : "=r"(r) : "r"(a), "r"(b));
    return r;
}
__device__ __forceinline__ uint32_t hsub2(uint32_t a, uint32_t b) {
    uint32_t r;
    asm("sub.rn.f16x2 %0, %1, %2;" : "=r"(r) : "r"(a), "r"(b));
    return r;
}
__device__ __forceinline__ uint32_t ex2h2(uint32_t a) {
    uint32_t r;
    asm("ex2.approx.f16x2 %0, %1;" : "=r"(r) : "r"(a));
    return r;
}
// VALUE-LEVEL f16x2 -> two f32 (no address-of: keeps register arrays promoted)
__device__ __forceinline__ float2 h2f2v(uint32_t u) {
    float x, y;
    asm("{ .reg .f16 lo, hi; mov.b32 {lo, hi}, %2; "
        "cvt.f32.f16 %0, lo; cvt.f32.f16 %1, hi; }"
        : "=f"(x), "=f"(y) : "r"(u));
    return make_float2(x, y);
}

// ---------------------------------------------------------------------------
// Merged fp32->fp16 convert: x (2M float4 chunks) + 4 weights (256K chunks ea)
__global__ void cvt_all(const float* __restrict__ x,
                        const float* __restrict__ wq, const float* __restrict__ wk,
                        const float* __restrict__ wv, const float* __restrict__ wo,
                        __half* __restrict__ xh, __half* __restrict__ wh)
{
    const int i = blockIdx.x * blockDim.x + threadIdx.x;   // 0..3145727
    const float* src;
    uint32_t* dst;
    int off;
    if (i < 2097152) {
        src = x; off = i; dst = (uint32_t*)xh;
    } else {
        const int j = i - 2097152;
        const int r = j >> 18;
        off = j & 262143;
        src = (r == 0) ? wq : (r == 1) ? wk : (r == 2) ? wv : wo;
        dst = (uint32_t*)(wh + ((size_t)r << 20));
    }
    const float4 v = ((const float4*)src)[off];
    dst[2 * off + 0] = packh2(v.x, v.y);
    dst[2 * off + 1] = packh2(v.z, v.w);
}

// ---------------------------------------------------------------------------
// Shared GEMM mainloop (128x128 tile): 3-stage cp.async, one barrier/stage,
// distance-1 fragment prefetch (R12 exact).
// ---------------------------------------------------------------------------
#define GS 32768
#define GEMM_SMEM (3 * GS)

struct GemmCtx {
    uint32_t sb;
    int tid, wid, lane, wm, wn;
};

__device__ __forceinline__ void gemm_mainloop(
    const GemmCtx& cx, const __half* __restrict__ A, const __half* __restrict__ W,
    int m0, int n0, float acc[2][8][4])
{
    const int tid = cx.tid, lane = cx.lane, wm = cx.wm, wn = cx.wn;
    const uint32_t sb = cx.sb;

    int goff[4], soff[4];
#pragma unroll
    for (int i = 0; i < 4; i++) {
        const int id = tid + (i << 8), r = id >> 3, c = id & 7;
        goff[i] = r * 1024 + c * 8;
        soff[i] = r * 128 + ((c * 16) ^ ((r & 7) << 4));
    }
    auto load_stage = [&](const __half* ga, const __half* gb, int buf) {
        const uint32_t sA = sb + buf * GS, sB = sA + 16384;
#pragma unroll
        for (int i = 0; i < 4; i++) CP16(sA + soff[i], ga + goff[i]);
#pragma unroll
        for (int i = 0; i < 4; i++) CP16(sB + soff[i], gb + goff[i]);
    };

    const __half* ap = A + (size_t)m0 * 1024;
    const __half* wp = W + (size_t)n0 * 1024;
    load_stage(ap, wp, 0); CP_COMMIT(); ap += 64; wp += 64;
    load_stage(ap, wp, 1); CP_COMMIT(); ap += 64; wp += 64;

    const int la15 = lane & 15;
    const int lbr  = ((lane >> 4) << 3) + (lane & 7);
    const uint32_t axy = (uint32_t)(((lane >> 4) << 4) ^ ((la15 & 7) << 4));
    const uint32_t bxy = (uint32_t)((((lane >> 3) & 1) << 4) ^ ((lbr & 7) << 4));
    const int aoff0 = (wm + la15) * 128, aoff1 = (wm + 16 + la15) * 128;
    const int boff  = (wn + lbr) * 128;

    int cbuf = 0, lbuf = 2;
    for (int s = 0; s < 16; s++) {
        if (s < 15) CP_WAIT1(); else CP_WAIT0();
        __syncthreads();
        if (s + 2 < 16) { load_stage(ap, wp, lbuf); CP_COMMIT(); ap += 64; wp += 64; }

        const uint32_t sA = sb + cbuf * GS, sB = sA + 16384;
        auto ldA = [&](uint32_t a[2][4], int kd) {
            const uint32_t kk = (uint32_t)(kd * 32) ^ axy;
            ldsm4(a[0], sA + aoff0 + kk);
            ldsm4(a[1], sA + aoff1 + kk);
        };
        auto ldB = [&](uint32_t b[4], int kd, int nt2) {
            ldsm4(b, sB + boff + nt2 * 2048 + ((uint32_t)(kd * 32) ^ bxy));
        };

        uint32_t a[2][2][4], b[2][4];
        ldA(a[0], 0);
        ldB(b[0], 0, 0);
#pragma unroll
        for (int step = 0; step < 16; step++) {
            const int kd = step >> 2, nt2 = step & 3;
            const int cb = step & 1, ab = kd & 1;
            if (step < 15) ldB(b[cb ^ 1], (step + 1) >> 2, (step + 1) & 3);
            if (nt2 == 1 && kd < 3) ldA(a[ab ^ 1], kd + 1);
#pragma unroll
            for (int mt = 0; mt < 2; mt++) {
                mma16816(acc[mt][nt2 * 2 + 0], a[ab][mt], b[cb][0], b[cb][1]);
                mma16816(acc[mt][nt2 * 2 + 1], a[ab][mt], b[cb][2], b[cb][3]);
            }
        }
        cbuf = (cbuf == 2) ? 0 : cbuf + 1;
        lbuf = (lbuf == 2) ? 0 : lbuf + 1;
    }
}

// Merged Q/K/V projection: grid.z selects weight/bias/output. fp16 head layout.
__global__ void __launch_bounds__(256, 2)
gemm_qkv(const __half* __restrict__ A, const __half* __restrict__ Wbase,
         const float* __restrict__ bq, const float* __restrict__ bk,
         const float* __restrict__ bv,
         __half* __restrict__ Cq, __half* __restrict__ Ck, __half* __restrict__ Cv)
{
    extern __shared__ char smem[];
    GemmCtx cx;
    cx.sb = smem_u32(smem);
    cx.tid = threadIdx.x; cx.wid = cx.tid >> 5; cx.lane = cx.tid & 31;
    cx.wm = (cx.wid & 3) << 5; cx.wn = (cx.wid >> 2) << 6;
    const int m0 = blockIdx.y << 7, n0 = blockIdx.x << 7;
    const int z = blockIdx.z;
    const __half* W = Wbase + ((size_t)z << 20);
    const float* bias = (z == 0) ? bq : (z == 1) ? bk : bv;
    __half* C = (z == 0) ? Cq : (z == 1) ? Ck : Cv;
    const float scale = (z == 0) ? CEXP : 1.0f;

    float acc[2][8][4];
#pragma unroll
    for (int mt = 0; mt < 2; mt++)
#pragma unroll
        for (int nt = 0; nt < 8; nt++)
#pragma unroll
            for (int c = 0; c < 4; c++) acc[mt][nt][c] = 0.f;

    gemm_mainloop(cx, A, W, m0, n0, acc);

    const int r0 = cx.lane >> 2, colq = (cx.lane & 3) * 2;
#pragma unroll
    for (int mt = 0; mt < 2; mt++) {
        const int row0 = m0 + cx.wm + mt * 16 + r0;
#pragma unroll
        for (int nt = 0; nt < 8; nt++) {
            const int col = n0 + cx.wn + nt * 8 + colq;
            const float2 bvv = *(const float2*)(bias + col);
            const float v0 = (acc[mt][nt][0] + bvv.x) * scale;
            const float v1 = (acc[mt][nt][1] + bvv.y) * scale;
            const float v2 = (acc[mt][nt][2] + bvv.x) * scale;
            const float v3 = (acc[mt][nt][3] + bvv.y) * scale;
            const int b = row0 >> 11, h = col >> 6, d = col & 63;
            const size_t hb = (size_t)(((b << 4) + h) << 11);
            *(uint32_t*)(C + (hb + (row0 & 2047)) * 64 + d)       = packh2(v0, v1);
            *(uint32_t*)(C + (hb + ((row0 + 8) & 2047)) * 64 + d) = packh2(v2, v3);
        }
    }
}

// Output projection: fp32 row-major out. (R12 128x128 version)
__global__ void __launch_bounds__(256, 2)
gemm_o(const __half* __restrict__ A, const __half* __restrict__ W,
       const float* __restrict__ bias, float* __restrict__ C)
{
    extern __shared__ char smem[];
    GemmCtx cx;
    cx.sb = smem_u32(smem);
    cx.tid = threadIdx.x; cx.wid = cx.tid >> 5; cx.lane = cx.tid & 31;
    cx.wm = (cx.wid & 3) << 5; cx.wn = (cx.wid >> 2) << 6;
    const int m0 = blockIdx.y << 7, n0 = blockIdx.x << 7;

    float acc[2][8][4];
#pragma unroll
    for (int mt = 0; mt < 2; mt++)
#pragma unroll
        for (int nt = 0; nt < 8; nt++)
#pragma unroll
            for (int c = 0; c < 4; c++) acc[mt][nt][c] = 0.f;

    gemm_mainloop(cx, A, W, m0, n0, acc);

    const int r0 = cx.lane >> 2, colq = (cx.lane & 3) * 2;
#pragma unroll
    for (int mt = 0; mt < 2; mt++) {
        const int row0 = m0 + cx.wm + mt * 16 + r0;
#pragma unroll
        for (int nt = 0; nt < 8; nt++) {
            const int col = n0 + cx.wn + nt * 8 + colq;
            const float2 bvv = *(const float2*)(bias + col);
            *(float2*)(C + (size_t)row0 * 1024 + col) =
                make_float2(acc[mt][nt][0] + bvv.x, acc[mt][nt][1] + bvv.y);
            *(float2*)(C + (size_t)(row0 + 8) * 1024 + col) =
                make_float2(acc[mt][nt][2] + bvv.x, acc[mt][nt][3] + bvv.y);
        }
    }
}

// ---------------------------------------------------------------------------
// Flash attention (R12 structure): fp16 HMMA, 64-key subtiles, 4-stage ring,
// one barrier per PAIR, f16x2 softmax; row sums now on FMA pipe via
// VALUE-LEVEL f16x2 unpack (removes 4 sum-MMAs/tile = 11% of tensor ops).
// 2 CTAs/SM.
// ---------------------------------------------------------------------------
#define FS 16384                     // bytes per KV stage (K 8K + V 8K), 64 keys
#define FLASH_SMEM (16384 + 4 * FS)  // Q 16K + 4 stages = 80K

__global__ void __launch_bounds__(256, 2)
flash_hmma(const __half* __restrict__ Q, const __half* __restrict__ K,
           const __half* __restrict__ V, __half* __restrict__ O)
{
    extern __shared__ char smem[];
    const uint32_t sb = smem_u32(smem);
    const uint32_t sQ = sb, sKV = sb + 16384;       // 4 stages of [K 8K | V 8K]
    const int tid = threadIdx.x, wid = tid >> 5, lane = tid & 31;
    const int q0 = blockIdx.x << 7, bh = blockIdx.y;
    const size_t base = (size_t)bh * (2048 * 64);
    const __half* Qb = Q + base + (size_t)q0 * 64;

    int g0, g1, s0, s1;
    {
        const int r0_ = tid >> 3, c_ = tid & 7;
        const int r1_ = (tid + 256) >> 3;
        g0 = r0_ * 64 + c_ * 8;  s0 = r0_ * 128 + ((c_ * 16) ^ ((r0_ & 7) << 4));
        g1 = r1_ * 64 + c_ * 8;  s1 = r1_ * 128 + ((c_ * 16) ^ ((r1_ & 7) << 4));
    }

#pragma unroll
    for (int i = 0; i < 4; i++) {                   // Q tile: 128 x 64 halves
        const int id = tid + (i << 8), r = id >> 3, c = id & 7;
        CP16(sQ + r * 128 + ((c * 16) ^ ((r & 7) << 4)), Qb + (size_t)r * 64 + c * 8);
    }
    auto load_kv = [&](const __half* kp, const __half* vp, int buf) {
        const uint32_t ks_ = sKV + buf * FS, vs_ = ks_ + 8192;
        CP16(ks_ + s0, kp + g0);
        CP16(ks_ + s1, kp + g1);
        CP16(vs_ + s0, vp + g0);
        CP16(vs_ + s1, vp + g1);
    };
    const __half* kp = K + base;
    const __half* vp = V + base;
    load_kv(kp, vp, 0); CP_COMMIT();                // g0 incl Q
    load_kv(kp + 4096, vp + 4096, 1); CP_COMMIT();
    kp += 8192; vp += 8192;
    CP_WAIT0();
    __syncthreads();

    uint32_t qf[4][4];
#pragma unroll
    for (int kd = 0; kd < 4; kd++) {
        const int r = (wid << 4) + (lane & 15);
        const int cb = kd * 32 + ((lane >> 4) << 4);
        ldsm4(qf[kd], sQ + r * 128 + (cb ^ ((r & 7) << 4)));
    }

    const int klr  = ((lane >> 4) << 3) + (lane & 7);
    const int koff = klr * 128;
    const uint32_t kxy = (uint32_t)((((lane >> 3) & 1) << 4) ^ ((klr & 7) << 4));
    const int voff = (lane & 15) * 128;
    const uint32_t vxy = (uint32_t)(((lane >> 4) << 4) ^ ((lane & 7) << 4));

    float oacc[8][4];
#pragma unroll
    for (int dn = 0; dn < 8; dn++)
#pragma unroll
        for (int c = 0; c < 4; c++) oacc[dn][c] = 0.f;
    uint32_t mrp = 0xFC00FC00u;                     // (-inf, -inf) running max
    float l0 = 0.f, l1 = 0.f;

    auto attn_tile = [&](uint32_t ks_, uint32_t vs_) {
        float sacc[8][4];
#pragma unroll
        for (int nt = 0; nt < 8; nt++)
#pragma unroll
            for (int c = 0; c < 4; c++) sacc[nt][c] = 0.f;
        {
            uint32_t b[2][4];
            auto ldK = [&](uint32_t* bb, int step) {
                const int kd = step >> 2, nt2 = step & 3;
                ldsm4(bb, ks_ + koff + nt2 * 2048 + ((uint32_t)(kd * 32) ^ kxy));
            };
            ldK(b[0], 0);
#pragma unroll
            for (int step = 0; step < 16; step++) {
                const int nt2 = step & 3, cb = step & 1, kd = step >> 2;
                if (step < 15) ldK(b[cb ^ 1], step + 1);
                mma16816(sacc[nt2 * 2 + 0], qf[kd], b[cb][0], b[cb][1]);
                mma16816(sacc[nt2 * 2 + 1], qf[kd], b[cb][2], b[cb][3]);
            }
        }

        // --- f16x2 softmax ---
#pragma unroll
        for (int nt = 0; nt < 8; nt++) {
            sacc[nt][0] = __uint_as_float(packh2(sacc[nt][0], sacc[nt][1]));
            sacc[nt][2] = __uint_as_float(packh2(sacc[nt][2], sacc[nt][3]));
        }
        // prefetch first V fragments: LDSM latency hides under softmax chain
        uint32_t vb[2][4];
        ldsm4t(vb[0], vs_ + voff + (0 ^ vxy));
        // packed per-thread max trees
        uint32_t t0 = hmax2(__float_as_uint(sacc[0][0]), __float_as_uint(sacc[1][0]));
        uint32_t t1 = hmax2(__float_as_uint(sacc[2][0]), __float_as_uint(sacc[3][0]));
        uint32_t t2 = hmax2(__float_as_uint(sacc[4][0]), __float_as_uint(sacc[5][0]));
        uint32_t t3 = hmax2(__float_as_uint(sacc[6][0]), __float_as_uint(sacc[7][0]));
        uint32_t m0 = hmax2(hmax2(t0, t1), hmax2(t2, t3));
        t0 = hmax2(__float_as_uint(sacc[0][2]), __float_as_uint(sacc[1][2]));
        t1 = hmax2(__float_as_uint(sacc[2][2]), __float_as_uint(sacc[3][2]));
        t2 = hmax2(__float_as_uint(sacc[4][2]), __float_as_uint(sacc[5][2]));
        t3 = hmax2(__float_as_uint(sacc[6][2]), __float_as_uint(sacc[7][2]));
        uint32_t m1 = hmax2(hmax2(t0, t1), hmax2(t2, t3));
        m0 = hmax2(m0, __byte_perm(m0, 0, 0x1032));
        m1 = hmax2(m1, __byte_perm(m1, 0, 0x1032));
        uint32_t mp = __byte_perm(m0, m1, 0x7610);    // (row0max, row1max)
        mp = hmax2(mp, __shfl_xor_sync(0xffffffffu, mp, 1));
        mp = hmax2(mp, __shfl_xor_sync(0xffffffffu, mp, 2));
        const uint32_t mold = mrp;
        const uint32_t mn = hmax2(mold, mp);
        mrp = mn;
        const uint32_t alp = ex2h2(hsub2(mold, mn));
        const float2 alf = h2f2v(alp);
        if (!__all_sync(0xffffffffu, mn == mold)) {
#pragma unroll
            for (int dn = 0; dn < 8; dn++) {
                oacc[dn][0] *= alf.x; oacc[dn][1] *= alf.x;
                oacc[dn][2] *= alf.y; oacc[dn][3] *= alf.y;
            }
        }
        const uint32_t mn0 = __byte_perm(mn, 0, 0x1010);
        const uint32_t mn1 = __byte_perm(mn, 0, 0x3232);
        // exp + fp32 row sums (value-level unpack, FMA pipe; no sum-MMAs)
        float rs0 = 0.f, rs1 = 0.f;
#pragma unroll
        for (int nt = 0; nt < 8; nt++) {
            const uint32_t p0 = ex2h2(hsub2(__float_as_uint(sacc[nt][0]), mn0));
            const uint32_t p1 = ex2h2(hsub2(__float_as_uint(sacc[nt][2]), mn1));
            sacc[nt][0] = __uint_as_float(p0);
            sacc[nt][2] = __uint_as_float(p1);
            const float2 f0 = h2f2v(p0);
            const float2 f1 = h2f2v(p1);
            rs0 += f0.x + f0.y;
            rs1 += f1.x + f1.y;
        }
        rs0 += __shfl_xor_sync(0xffffffffu, rs0, 1);
        rs0 += __shfl_xor_sync(0xffffffffu, rs0, 2);
        rs1 += __shfl_xor_sync(0xffffffffu, rs1, 1);
        rs1 += __shfl_xor_sync(0xffffffffu, rs1, 2);

        // O += P V  (16 MMAs; sum-MMA chain removed)
        {
            uint32_t a[4];
            auto ldVt = [&](uint32_t* bb, int step) {
                const int ks = step >> 2, dn2 = step & 3;
                ldsm4t(bb, vs_ + voff + ks * 2048 + ((uint32_t)(dn2 * 32) ^ vxy));
            };
#pragma unroll
            for (int step = 0; step < 16; step++) {
                const int ks = step >> 2, dn2 = step & 3, cb = step & 1;
                if (step < 15) ldVt(vb[cb ^ 1], step + 1);
                if (dn2 == 0) {
                    a[0] = __float_as_uint(sacc[2 * ks][0]);
                    a[1] = __float_as_uint(sacc[2 * ks][2]);
                    a[2] = __float_as_uint(sacc[2 * ks + 1][0]);
                    a[3] = __float_as_uint(sacc[2 * ks + 1][2]);
                }
                mma16816(oacc[dn2 * 2 + 0], a, vb[cb][0], vb[cb][1]);
                mma16816(oacc[dn2 * 2 + 1], a, vb[cb][2], vb[cb][3]);
            }
        }
        l0 = l0 * alf.x + rs0;
        l1 = l1 * alf.y + rs1;
    };

    // main loop: 16 pairs of 64-key tiles; one wait+barrier per pair
    for (int p = 0; p < 16; p++) {
        if (p > 0) {
            CP_WAIT0();
            __syncthreads();
        }
        if (p < 15) {
            load_kv(kp, vp, (2 * p + 2) & 3); CP_COMMIT();
            load_kv(kp + 4096, vp + 4096, (2 * p + 3) & 3); CP_COMMIT();
            kp += 8192; vp += 8192;
        }
        const uint32_t b0 = sKV + ((2 * p) & 3) * FS;
        const uint32_t b1 = sKV + ((2 * p + 1) & 3) * FS;
        attn_tile(b0, b0 + 8192);
        attn_tile(b1, b1 + 8192);
    }

    // normalize + write packed [b][s][h*64+d] fp16
    const int b_ = bh >> 4, h_ = bh & 15;
    __half* Ob = O + ((size_t)b_ * 2048 + q0) * 1024 + h_ * 64;
    const float inv0 = 1.f / l0, inv1 = 1.f / l1;
    const int r0 = (wid << 4) + (lane >> 2), colq = (lane & 3) * 2;
#pragma unroll
    for (int dn = 0; dn < 8; dn++) {
        const int col = dn * 8 + colq;
        *(uint32_t*)(Ob + (size_t)r0 * 1024 + col) =
            packh2(oacc[dn][0] * inv0, oacc[dn][1] * inv0);
        *(uint32_t*)(Ob + (size_t)(r0 + 8) * 1024 + col) =
            packh2(oacc[dn][2] * inv1, oacc[dn][3] * inv1);
    }
}

// ---------------------------------------------------------------------------
extern "C" void kernel_launch(void* const* d_in, const int* in_sizes, int n_in,
                              void* d_out, int out_size)
{
    const float* x  = (const float*)d_in[0];
    const float* wq = (const float*)d_in[1];
    const float* bq = (const float*)d_in[2];
    const float* wk = (const float*)d_in[3];
    const float* bk = (const float*)d_in[4];
    const float* wv = (const float*)d_in[5];
    const float* bv = (const float*)d_in[6];
    const float* wo = (const float*)d_in[7];
    const float* bo = (const float*)d_in[8];
    float* out = (float*)d_out;

    __half *xh, *wh, *qh, *kh, *vh, *aoh;
    cudaGetSymbolAddress((void**)&xh,  g_xh);
    cudaGetSymbolAddress((void**)&wh,  g_wh);
    cudaGetSymbolAddress((void**)&qh,  g_qh);
    cudaGetSymbolAddress((void**)&kh,  g_kh);
    cudaGetSymbolAddress((void**)&vh,  g_vh);
    cudaGetSymbolAddress((void**)&aoh, g_aoh);

    cudaFuncSetAttribute(gemm_qkv, cudaFuncAttributeMaxDynamicSharedMemorySize, GEMM_SMEM);
    cudaFuncSetAttribute(gemm_o,   cudaFuncAttributeMaxDynamicSharedMemorySize, GEMM_SMEM);
    cudaFuncSetAttribute(flash_hmma, cudaFuncAttributeMaxDynamicSharedMemorySize, FLASH_SMEM);

    cvt_all<<<12288, 256>>>(x, wq, wk, wv, wo, xh, wh);

    gemm_qkv<<<dim3(8, 64, 3), 256, GEMM_SMEM>>>(xh, wh, bq, bk, bv, qh, kh, vh);
    flash_hmma<<<dim3(16, 64), 256, FLASH_SMEM>>>(qh, kh, vh, aoh);
    gemm_o<<<dim3(8, 64), 256, GEMM_SMEM>>>(aoh, wh + 3145728, bo, out);
}

// round 16
// speedup vs baseline: 1.0278x; 1.0278x over previous
#include <cuda_runtime.h>
#include <cuda_fp16.h>
#include <cstdint>

#define CEXP 0.18033688011112042f   // 0.125 * log2(e), folded into Q projection

// fp16 scratch
static __device__ __align__(16) __half g_xh[8388608];   // x as fp16
static __device__ __align__(16) __half g_wh[4194304];   // wq|wk|wv|wo as fp16
static __device__ __align__(16) __half g_qh[8388608];   // [b][h][s][d], pre-scaled by CEXP
static __device__ __align__(16) __half g_kh[8388608];
static __device__ __align__(16) __half g_vh[8388608];
static __device__ __align__(16) __half g_aoh[8388608];  // [b][s][h*d]

// ---------------------------------------------------------------------------
__device__ __forceinline__ uint32_t smem_u32(const void* p) {
    uint32_t a;
    asm("{ .reg .u64 t; cvta.to.shared.u64 t, %1; cvt.u32.u64 %0, t; }" : "=r"(a) : "l"(p));
    return a;
}
#define CP16(s, g) asm volatile("cp.async.cg.shared.global [%0], [%1], 16;" :: "r"(s), "l"(g))
#define CP_COMMIT() asm volatile("cp.async.commit_group;" ::: "memory")
#define CP_WAIT0()  asm volatile("cp.async.wait_group 0;" ::: "memory")
#define CP_WAIT1()  asm volatile("cp.async.wait_group 1;" ::: "memory")

__device__ __forceinline__ void ldsm4(uint32_t* r, uint32_t a) {
    asm volatile("ldmatrix.sync.aligned.m8n8.x4.shared.b16 {%0,%1,%2,%3}, [%4];"
                 : "=r"(r[0]), "=r"(r[1]), "=r"(r[2]), "=r"(r[3]) : "r"(a));
}
__device__ __forceinline__ void ldsm4t(uint32_t* r, uint32_t a) {
    asm volatile("ldmatrix.sync.aligned.m8n8.x4.trans.shared.b16 {%0,%1,%2,%3}, [%4];"
                 : "=r"(r[0]), "=r"(r[1]), "=r"(r[2]), "=r"(r[3]) : "r"(a));
}
__device__ __forceinline__ void mma16816(float* c, const uint32_t* a, uint32_t b0, uint32_t b1) {
    asm volatile("mma.sync.aligned.m16n8k16.row.col.f32.f16.f16.f32 "
                 "{%0,%1,%2,%3}, {%4,%5,%6,%7}, {%8,%9}, {%0,%1,%2,%3};"
                 : "+f"(c[0]), "+f"(c[1]), "+f"(c[2]), "+f"(c[3])
                 : "r"(a[0]), "r"(a[1]), "r"(a[2]), "r"(a[3]), "r"(b0), "r"(b1));
}
__device__ __forceinline__ uint32_t packh2(float lo, float hi) {
    uint32_t r;
    asm("cvt.rn.f16x2.f32 %0, %1, %2;" : "=r"(r) : "f"(hi), "f"(lo));
    return r;
}
__device__ __forceinline__ uint32_t hmax2(uint32_t a, uint32_t b) {
    uint32_t r;
    asm("max.f16x2 %0, %1, %2;" : "=r"(r) : "r"(a), "r"(b));
    return r;
}
__device__ __forceinline__ uint32_t hsub2(uint32_t a, uint32_t b) {
    uint32_t r;
    asm("sub.rn.f16x2 %0, %1, %2;" : "=r"(r) : "r"(a), "r"(b));
    return r;
}
__device__ __forceinline__ uint32_t ex2h2(uint32_t a) {
    uint32_t r;
    asm("ex2.approx.f16x2 %0, %1;" : "=r"(r) : "r"(a));
    return r;
}

// ---------------------------------------------------------------------------
// Merged fp32->fp16 convert: x (2M float4 chunks) + 4 weights (256K chunks ea)
__global__ void cvt_all(const float* __restrict__ x,
                        const float* __restrict__ wq, const float* __restrict__ wk,
                        const float* __restrict__ wv, const float* __restrict__ wo,
                        __half* __restrict__ xh, __half* __restrict__ wh)
{
    const int i = blockIdx.x * blockDim.x + threadIdx.x;   // 0..3145727
    const float* src;
    uint32_t* dst;
    int off;
    if (i < 2097152) {
        src = x; off = i; dst = (uint32_t*)xh;
    } else {
        const int j = i - 2097152;
        const int r = j >> 18;
        off = j & 262143;
        src = (r == 0) ? wq : (r == 1) ? wk : (r == 2) ? wv : wo;
        dst = (uint32_t*)(wh + ((size_t)r << 20));
    }
    const float4 v = ((const float4*)src)[off];
    dst[2 * off + 0] = packh2(v.x, v.y);
    dst[2 * off + 1] = packh2(v.z, v.w);
}

// ---------------------------------------------------------------------------
// Shared GEMM mainloop: 128x128 tile, 3-stage cp.async, one barrier/stage,
// distance-1 fragment prefetch (R12 exact).
// ---------------------------------------------------------------------------
#define GS 32768
#define GEMM_SMEM (3 * GS)

struct GemmCtx {
    uint32_t sb;
    int tid, wid, lane, wm, wn;
};

__device__ __forceinline__ void gemm_mainloop(
    const GemmCtx& cx, const __half* __restrict__ A, const __half* __restrict__ W,
    int m0, int n0, float acc[2][8][4])
{
    const int tid = cx.tid, lane = cx.lane, wm = cx.wm, wn = cx.wn;
    const uint32_t sb = cx.sb;

    int goff[4], soff[4];
#pragma unroll
    for (int i = 0; i < 4; i++) {
        const int id = tid + (i << 8), r = id >> 3, c = id & 7;
        goff[i] = r * 1024 + c * 8;
        soff[i] = r * 128 + ((c * 16) ^ ((r & 7) << 4));
    }
    auto load_stage = [&](const __half* ga, const __half* gb, int buf) {
        const uint32_t sA = sb + buf * GS, sB = sA + 16384;
#pragma unroll
        for (int i = 0; i < 4; i++) CP16(sA + soff[i], ga + goff[i]);
#pragma unroll
        for (int i = 0; i < 4; i++) CP16(sB + soff[i], gb + goff[i]);
    };

    const __half* ap = A + (size_t)m0 * 1024;
    const __half* wp = W + (size_t)n0 * 1024;
    load_stage(ap, wp, 0); CP_COMMIT(); ap += 64; wp += 64;
    load_stage(ap, wp, 1); CP_COMMIT(); ap += 64; wp += 64;

    const int la15 = lane & 15;
    const int lbr  = ((lane >> 4) << 3) + (lane & 7);
    const uint32_t axy = (uint32_t)(((lane >> 4) << 4) ^ ((la15 & 7) << 4));
    const uint32_t bxy = (uint32_t)((((lane >> 3) & 1) << 4) ^ ((lbr & 7) << 4));
    const int aoff0 = (wm + la15) * 128, aoff1 = (wm + 16 + la15) * 128;
    const int boff  = (wn + lbr) * 128;

    int cbuf = 0, lbuf = 2;
    for (int s = 0; s < 16; s++) {
        if (s < 15) CP_WAIT1(); else CP_WAIT0();
        __syncthreads();
        if (s + 2 < 16) { load_stage(ap, wp, lbuf); CP_COMMIT(); ap += 64; wp += 64; }

        const uint32_t sA = sb + cbuf * GS, sB = sA + 16384;
        auto ldA = [&](uint32_t a[2][4], int kd) {
            const uint32_t kk = (uint32_t)(kd * 32) ^ axy;
            ldsm4(a[0], sA + aoff0 + kk);
            ldsm4(a[1], sA + aoff1 + kk);
        };
        auto ldB = [&](uint32_t b[4], int kd, int nt2) {
            ldsm4(b, sB + boff + nt2 * 2048 + ((uint32_t)(kd * 32) ^ bxy));
        };

        uint32_t a[2][2][4], b[2][4];
        ldA(a[0], 0);
        ldB(b[0], 0, 0);
#pragma unroll
        for (int step = 0; step < 16; step++) {
            const int kd = step >> 2, nt2 = step & 3;
            const int cb = step & 1, ab = kd & 1;
            if (step < 15) ldB(b[cb ^ 1], (step + 1) >> 2, (step + 1) & 3);
            if (nt2 == 1 && kd < 3) ldA(a[ab ^ 1], kd + 1);
#pragma unroll
            for (int mt = 0; mt < 2; mt++) {
                mma16816(acc[mt][nt2 * 2 + 0], a[ab][mt], b[cb][0], b[cb][1]);
                mma16816(acc[mt][nt2 * 2 + 1], a[ab][mt], b[cb][2], b[cb][3]);
            }
        }
        cbuf = (cbuf == 2) ? 0 : cbuf + 1;
        lbuf = (lbuf == 2) ? 0 : lbuf + 1;
    }
}

// Merged Q/K/V projection: grid.z selects weight/bias/output. fp16 head layout.
__global__ void __launch_bounds__(256, 2)
gemm_qkv(const __half* __restrict__ A, const __half* __restrict__ Wbase,
         const float* __restrict__ bq, const float* __restrict__ bk,
         const float* __restrict__ bv,
         __half* __restrict__ Cq, __half* __restrict__ Ck, __half* __restrict__ Cv)
{
    cudaGridDependencySynchronize();               // PDL: wait for cvt_all
    extern __shared__ char smem[];
    GemmCtx cx;
    cx.sb = smem_u32(smem);
    cx.tid = threadIdx.x; cx.wid = cx.tid >> 5; cx.lane = cx.tid & 31;
    cx.wm = (cx.wid & 3) << 5; cx.wn = (cx.wid >> 2) << 6;
    const int m0 = blockIdx.y << 7, n0 = blockIdx.x << 7;
    const int z = blockIdx.z;
    const __half* W = Wbase + ((size_t)z << 20);
    const float* bias = (z == 0) ? bq : (z == 1) ? bk : bv;
    __half* C = (z == 0) ? Cq : (z == 1) ? Ck : Cv;
    const float scale = (z == 0) ? CEXP : 1.0f;

    float acc[2][8][4];
#pragma unroll
    for (int mt = 0; mt < 2; mt++)
#pragma unroll
        for (int nt = 0; nt < 8; nt++)
#pragma unroll
            for (int c = 0; c < 4; c++) acc[mt][nt][c] = 0.f;

    gemm_mainloop(cx, A, W, m0, n0, acc);

    const int r0 = cx.lane >> 2, colq = (cx.lane & 3) * 2;
#pragma unroll
    for (int mt = 0; mt < 2; mt++) {
        const int row0 = m0 + cx.wm + mt * 16 + r0;
#pragma unroll
        for (int nt = 0; nt < 8; nt++) {
            const int col = n0 + cx.wn + nt * 8 + colq;
            const float2 bvv = *(const float2*)(bias + col);
            const float v0 = (acc[mt][nt][0] + bvv.x) * scale;
            const float v1 = (acc[mt][nt][1] + bvv.y) * scale;
            const float v2 = (acc[mt][nt][2] + bvv.x) * scale;
            const float v3 = (acc[mt][nt][3] + bvv.y) * scale;
            const int b = row0 >> 11, h = col >> 6, d = col & 63;
            const size_t hb = (size_t)(((b << 4) + h) << 11);
            *(uint32_t*)(C + (hb + (row0 & 2047)) * 64 + d)       = packh2(v0, v1);
            *(uint32_t*)(C + (hb + ((row0 + 8) & 2047)) * 64 + d) = packh2(v2, v3);
        }
    }
}

// Output projection: fp32 row-major out.
__global__ void __launch_bounds__(256, 2)
gemm_o(const __half* __restrict__ A, const __half* __restrict__ W,
       const float* __restrict__ bias, float* __restrict__ C)
{
    cudaGridDependencySynchronize();               // PDL: wait for flash_hmma
    extern __shared__ char smem[];
    GemmCtx cx;
    cx.sb = smem_u32(smem);
    cx.tid = threadIdx.x; cx.wid = cx.tid >> 5; cx.lane = cx.tid & 31;
    cx.wm = (cx.wid & 3) << 5; cx.wn = (cx.wid >> 2) << 6;
    const int m0 = blockIdx.y << 7, n0 = blockIdx.x << 7;

    float acc[2][8][4];
#pragma unroll
    for (int mt = 0; mt < 2; mt++)
#pragma unroll
        for (int nt = 0; nt < 8; nt++)
#pragma unroll
            for (int c = 0; c < 4; c++) acc[mt][nt][c] = 0.f;

    gemm_mainloop(cx, A, W, m0, n0, acc);

    const int r0 = cx.lane >> 2, colq = (cx.lane & 3) * 2;
#pragma unroll
    for (int mt = 0; mt < 2; mt++) {
        const int row0 = m0 + cx.wm + mt * 16 + r0;
#pragma unroll
        for (int nt = 0; nt < 8; nt++) {
            const int col = n0 + cx.wn + nt * 8 + colq;
            const float2 bvv = *(const float2*)(bias + col);
            *(float2*)(C + (size_t)row0 * 1024 + col) =
                make_float2(acc[mt][nt][0] + bvv.x, acc[mt][nt][1] + bvv.y);
            *(float2*)(C + (size_t)(row0 + 8) * 1024 + col) =
                make_float2(acc[mt][nt][2] + bvv.x, acc[mt][nt][3] + bvv.y);
        }
    }
}

// ---------------------------------------------------------------------------
// Flash attention (R12 exact): fp16 HMMA, 64-key subtiles, 4-stage ring,
// one barrier per PAIR, f16x2 softmax, ones-B row-sum MMAs with two
// alternating accumulators, 2 CTAs/SM.
// ---------------------------------------------------------------------------
#define FS 16384                     // bytes per KV stage (K 8K + V 8K), 64 keys
#define FLASH_SMEM (16384 + 4 * FS)  // Q 16K + 4 stages = 80K

__global__ void __launch_bounds__(256, 2)
flash_hmma(const __half* __restrict__ Q, const __half* __restrict__ K,
           const __half* __restrict__ V, __half* __restrict__ O)
{
    cudaGridDependencySynchronize();               // PDL: wait for gemm_qkv
    extern __shared__ char smem[];
    const uint32_t sb = smem_u32(smem);
    const uint32_t sQ = sb, sKV = sb + 16384;       // 4 stages of [K 8K | V 8K]
    const int tid = threadIdx.x, wid = tid >> 5, lane = tid & 31;
    const int q0 = blockIdx.x << 7, bh = blockIdx.y;
    const size_t base = (size_t)bh * (2048 * 64);
    const __half* Qb = Q + base + (size_t)q0 * 64;
    const uint32_t ONES = 0x3C003C00u;

    int g0, g1, s0, s1;
    {
        const int r0_ = tid >> 3, c_ = tid & 7;
        const int r1_ = (tid + 256) >> 3;
        g0 = r0_ * 64 + c_ * 8;  s0 = r0_ * 128 + ((c_ * 16) ^ ((r0_ & 7) << 4));
        g1 = r1_ * 64 + c_ * 8;  s1 = r1_ * 128 + ((c_ * 16) ^ ((r1_ & 7) << 4));
    }

#pragma unroll
    for (int i = 0; i < 4; i++) {                   // Q tile: 128 x 64 halves
        const int id = tid + (i << 8), r = id >> 3, c = id & 7;
        CP16(sQ + r * 128 + ((c * 16) ^ ((r & 7) << 4)), Qb + (size_t)r * 64 + c * 8);
    }
    auto load_kv = [&](const __half* kp, const __half* vp, int buf) {
        const uint32_t ks_ = sKV + buf * FS, vs_ = ks_ + 8192;
        CP16(ks_ + s0, kp + g0);
        CP16(ks_ + s1, kp + g1);
        CP16(vs_ + s0, vp + g0);
        CP16(vs_ + s1, vp + g1);
    };
    const __half* kp = K + base;
    const __half* vp = V + base;
    load_kv(kp, vp, 0); CP_COMMIT();                // g0 incl Q
    load_kv(kp + 4096, vp + 4096, 1); CP_COMMIT();
    kp += 8192; vp += 8192;
    CP_WAIT0();
    __syncthreads();

    uint32_t qf[4][4];
#pragma unroll
    for (int kd = 0; kd < 4; kd++) {
        const int r = (wid << 4) + (lane & 15);
        const int cb = kd * 32 + ((lane >> 4) << 4);
        ldsm4(qf[kd], sQ + r * 128 + (cb ^ ((r & 7) << 4)));
    }

    const int klr  = ((lane >> 4) << 3) + (lane & 7);
    const int koff = klr * 128;
    const uint32_t kxy = (uint32_t)((((lane >> 3) & 1) << 4) ^ ((klr & 7) << 4));
    const int voff = (lane & 15) * 128;
    const uint32_t vxy = (uint32_t)(((lane >> 4) << 4) ^ ((lane & 7) << 4));

    float oacc[8][4];
#pragma unroll
    for (int dn = 0; dn < 8; dn++)
#pragma unroll
        for (int c = 0; c < 4; c++) oacc[dn][c] = 0.f;
    uint32_t mrp = 0xFC00FC00u;                     // (-inf, -inf) running max
    float l0 = 0.f, l1 = 0.f;

    auto attn_tile = [&](uint32_t ks_, uint32_t vs_) {
        float sacc[8][4];
#pragma unroll
        for (int nt = 0; nt < 8; nt++)
#pragma unroll
            for (int c = 0; c < 4; c++) sacc[nt][c] = 0.f;
        {
            uint32_t b[2][4];
            auto ldK = [&](uint32_t* bb, int step) {
                const int kd = step >> 2, nt2 = step & 3;
                ldsm4(bb, ks_ + koff + nt2 * 2048 + ((uint32_t)(kd * 32) ^ kxy));
            };
            ldK(b[0], 0);
#pragma unroll
            for (int step = 0; step < 16; step++) {
                const int nt2 = step & 3, cb = step & 1, kd = step >> 2;
                if (step < 15) ldK(b[cb ^ 1], step + 1);
                mma16816(sacc[nt2 * 2 + 0], qf[kd], b[cb][0], b[cb][1]);
                mma16816(sacc[nt2 * 2 + 1], qf[kd], b[cb][2], b[cb][3]);
            }
        }

        // --- f16x2 softmax ---
#pragma unroll
        for (int nt = 0; nt < 8; nt++) {
            sacc[nt][0] = __uint_as_float(packh2(sacc[nt][0], sacc[nt][1]));
            sacc[nt][2] = __uint_as_float(packh2(sacc[nt][2], sacc[nt][3]));
        }
        // prefetch first V fragments: LDSM latency hides under softmax chain
        uint32_t vb[2][4];
        ldsm4t(vb[0], vs_ + voff + (0 ^ vxy));
        // packed per-thread max trees
        uint32_t t0 = hmax2(__float_as_uint(sacc[0][0]), __float_as_uint(sacc[1][0]));
        uint32_t t1 = hmax2(__float_as_uint(sacc[2][0]), __float_as_uint(sacc[3][0]));
        uint32_t t2 = hmax2(__float_as_uint(sacc[4][0]), __float_as_uint(sacc[5][0]));
        uint32_t t3 = hmax2(__float_as_uint(sacc[6][0]), __float_as_uint(sacc[7][0]));
        uint32_t m0 = hmax2(hmax2(t0, t1), hmax2(t2, t3));
        t0 = hmax2(__float_as_uint(sacc[0][2]), __float_as_uint(sacc[1][2]));
        t1 = hmax2(__float_as_uint(sacc[2][2]), __float_as_uint(sacc[3][2]));
        t2 = hmax2(__float_as_uint(sacc[4][2]), __float_as_uint(sacc[5][2]));
        t3 = hmax2(__float_as_uint(sacc[6][2]), __float_as_uint(sacc[7][2]));
        uint32_t m1 = hmax2(hmax2(t0, t1), hmax2(t2, t3));
        m0 = hmax2(m0, __byte_perm(m0, 0, 0x1032));
        m1 = hmax2(m1, __byte_perm(m1, 0, 0x1032));
        uint32_t mp = __byte_perm(m0, m1, 0x7610);    // (row0max, row1max)
        mp = hmax2(mp, __shfl_xor_sync(0xffffffffu, mp, 1));
        mp = hmax2(mp, __shfl_xor_sync(0xffffffffu, mp, 2));
        const uint32_t mold = mrp;
        const uint32_t mn = hmax2(mold, mp);
        mrp = mn;
        const uint32_t alp = ex2h2(hsub2(mold, mn));
        const float2 alf = __half22float2(*(const __half2*)&alp);
        if (!__all_sync(0xffffffffu, mn == mold)) {
#pragma unroll
            for (int dn = 0; dn < 8; dn++) {
                oacc[dn][0] *= alf.x; oacc[dn][1] *= alf.x;
                oacc[dn][2] *= alf.y; oacc[dn][3] *= alf.y;
            }
        }
        const uint32_t mn0 = __byte_perm(mn, 0, 0x1010);
        const uint32_t mn1 = __byte_perm(mn, 0, 0x3232);
#pragma unroll
        for (int nt = 0; nt < 8; nt++) {
            sacc[nt][0] = __uint_as_float(ex2h2(hsub2(__float_as_uint(sacc[nt][0]), mn0)));
            sacc[nt][2] = __uint_as_float(ex2h2(hsub2(__float_as_uint(sacc[nt][2]), mn1)));
        }

        // O += P V; row sums via ones-B HMMA, two alternating accumulators
        float rsa[4] = {0.f, 0.f, 0.f, 0.f};
        float rsb[4] = {0.f, 0.f, 0.f, 0.f};
        {
            uint32_t a[4];
            auto ldVt = [&](uint32_t* bb, int step) {
                const int ks = step >> 2, dn2 = step & 3;
                ldsm4t(bb, vs_ + voff + ks * 2048 + ((uint32_t)(dn2 * 32) ^ vxy));
            };
#pragma unroll
            for (int step = 0; step < 16; step++) {
                const int ks = step >> 2, dn2 = step & 3, cb = step & 1;
                if (step < 15) ldVt(vb[cb ^ 1], step + 1);
                if (dn2 == 0) {
                    a[0] = __float_as_uint(sacc[2 * ks][0]);
                    a[1] = __float_as_uint(sacc[2 * ks][2]);
                    a[2] = __float_as_uint(sacc[2 * ks + 1][0]);
                    a[3] = __float_as_uint(sacc[2 * ks + 1][2]);
                    mma16816((ks & 1) ? rsb : rsa, a, ONES, ONES);
                }
                mma16816(oacc[dn2 * 2 + 0], a, vb[cb][0], vb[cb][1]);
                mma16816(oacc[dn2 * 2 + 1], a, vb[cb][2], vb[cb][3]);
            }
        }
        l0 = l0 * alf.x + (rsa[0] + rsb[0]);
        l1 = l1 * alf.y + (rsa[2] + rsb[2]);
    };

    // main loop: 16 pairs of 64-key tiles; one wait+barrier per pair
    for (int p = 0; p < 16; p++) {
        if (p > 0) {
            CP_WAIT0();
            __syncthreads();
        }
        if (p < 15) {
            load_kv(kp, vp, (2 * p + 2) & 3); CP_COMMIT();
            load_kv(kp + 4096, vp + 4096, (2 * p + 3) & 3); CP_COMMIT();
            kp += 8192; vp += 8192;
        }
        const uint32_t b0 = sKV + ((2 * p) & 3) * FS;
        const uint32_t b1 = sKV + ((2 * p + 1) & 3) * FS;
        attn_tile(b0, b0 + 8192);
        attn_tile(b1, b1 + 8192);
    }

    // normalize + write packed [b][s][h*64+d] fp16
    const int b_ = bh >> 4, h_ = bh & 15;
    __half* Ob = O + ((size_t)b_ * 2048 + q0) * 1024 + h_ * 64;
    const float inv0 = 1.f / l0, inv1 = 1.f / l1;
    const int r0 = (wid << 4) + (lane >> 2), colq = (lane & 3) * 2;
#pragma unroll
    for (int dn = 0; dn < 8; dn++) {
        const int col = dn * 8 + colq;
        *(uint32_t*)(Ob + (size_t)r0 * 1024 + col) =
            packh2(oacc[dn][0] * inv0, oacc[dn][1] * inv0);
        *(uint32_t*)(Ob + (size_t)(r0 + 8) * 1024 + col) =
            packh2(oacc[dn][2] * inv1, oacc[dn][3] * inv1);
    }
}

// ---------------------------------------------------------------------------
extern "C" void kernel_launch(void* const* d_in, const int* in_sizes, int n_in,
                              void* d_out, int out_size)
{
    const float* x  = (const float*)d_in[0];
    const float* wq = (const float*)d_in[1];
    const float* bq = (const float*)d_in[2];
    const float* wk = (const float*)d_in[3];
    const float* bk = (const float*)d_in[4];
    const float* wv = (const float*)d_in[5];
    const float* bv = (const float*)d_in[6];
    const float* wo = (const float*)d_in[7];
    const float* bo = (const float*)d_in[8];
    float* out = (float*)d_out;

    __half *xh, *wh, *qh, *kh, *vh, *aoh;
    cudaGetSymbolAddress((void**)&xh,  g_xh);
    cudaGetSymbolAddress((void**)&wh,  g_wh);
    cudaGetSymbolAddress((void**)&qh,  g_qh);
    cudaGetSymbolAddress((void**)&kh,  g_kh);
    cudaGetSymbolAddress((void**)&vh,  g_vh);
    cudaGetSymbolAddress((void**)&aoh, g_aoh);

    cudaFuncSetAttribute(gemm_qkv, cudaFuncAttributeMaxDynamicSharedMemorySize, GEMM_SMEM);
    cudaFuncSetAttribute(gemm_o,   cudaFuncAttributeMaxDynamicSharedMemorySize, GEMM_SMEM);
    cudaFuncSetAttribute(flash_hmma, cudaFuncAttributeMaxDynamicSharedMemorySize, FLASH_SMEM);

    cvt_all<<<12288, 256>>>(x, wq, wk, wv, wo, xh, wh);

    // PDL launches: downstream CTAs dispatch into upstream's tail wave and
    // block in cudaGridDependencySynchronize() until upstream completes.
    cudaLaunchAttribute at[1];
    at[0].id = cudaLaunchAttributeProgrammaticStreamSerialization;
    at[0].val.programmaticStreamSerializationAllowed = 1;

    {
        cudaLaunchConfig_t cfg = {};
        cfg.gridDim = dim3(8, 64, 3);
        cfg.blockDim = dim3(256, 1, 1);
        cfg.dynamicSmemBytes = GEMM_SMEM;
        cfg.stream = 0;
        cfg.attrs = at; cfg.numAttrs = 1;
        cudaLaunchKernelEx(&cfg, gemm_qkv, (const __half*)xh, (const __half*)wh,
                           bq, bk, bv, qh, kh, vh);
    }
    {
        cudaLaunchConfig_t cfg = {};
        cfg.gridDim = dim3(16, 64, 1);
        cfg.blockDim = dim3(256, 1, 1);
        cfg.dynamicSmemBytes = FLASH_SMEM;
        cfg.stream = 0;
        cfg.attrs = at; cfg.numAttrs = 1;
        cudaLaunchKernelEx(&cfg, flash_hmma, (const __half*)qh, (const __half*)kh,
                           (const __half*)vh, aoh);
    }
    {
        cudaLaunchConfig_t cfg = {};
        cfg.gridDim = dim3(8, 64, 1);
        cfg.blockDim = dim3(256, 1, 1);
        cfg.dynamicSmemBytes = GEMM_SMEM;
        cfg.stream = 0;
        cfg.attrs = at; cfg.numAttrs = 1;
        cudaLaunchKernelEx(&cfg, gemm_o, (const __half*)aoh,
                           (const __half*)(wh + 3145728), bo, out);
    }
}

// round 17
// speedup vs baseline: 1.0443x; 1.0160x over previous
#include <cuda_runtime.h>
#include <cuda_fp16.h>
#include <cstdint>

#define CEXP 0.18033688011112042f   // 0.125 * log2(e), folded into Q projection

// fp16 scratch
static __device__ __align__(16) __half g_xh[8388608];   // x as fp16
static __device__ __align__(16) __half g_wh[4194304];   // wq|wk|wv|wo as fp16
static __device__ __align__(16) __half g_qh[8388608];   // [b][h][s][d], pre-scaled by CEXP
static __device__ __align__(16) __half g_kh[8388608];
static __device__ __align__(16) __half g_vh[8388608];
static __device__ __align__(16) __half g_aoh[8388608];  // [b][s][h*d]

// ---------------------------------------------------------------------------
__device__ __forceinline__ uint32_t smem_u32(const void* p) {
    uint32_t a;
    asm("{ .reg .u64 t; cvta.to.shared.u64 t, %1; cvt.u32.u64 %0, t; }" : "=r"(a) : "l"(p));
    return a;
}
#define CP16(s, g) asm volatile("cp.async.cg.shared.global [%0], [%1], 16;" :: "r"(s), "l"(g))
#define CP_COMMIT() asm volatile("cp.async.commit_group;" ::: "memory")
#define CP_WAIT0()  asm volatile("cp.async.wait_group 0;" ::: "memory")
#define CP_WAIT1()  asm volatile("cp.async.wait_group 1;" ::: "memory")

__device__ __forceinline__ void ldsm4(uint32_t* r, uint32_t a) {
    asm volatile("ldmatrix.sync.aligned.m8n8.x4.shared.b16 {%0,%1,%2,%3}, [%4];"
                 : "=r"(r[0]), "=r"(r[1]), "=r"(r[2]), "=r"(r[3]) : "r"(a));
}
__device__ __forceinline__ void ldsm4t(uint32_t* r, uint32_t a) {
    asm volatile("ldmatrix.sync.aligned.m8n8.x4.trans.shared.b16 {%0,%1,%2,%3}, [%4];"
                 : "=r"(r[0]), "=r"(r[1]), "=r"(r[2]), "=r"(r[3]) : "r"(a));
}
__device__ __forceinline__ void mma16816(float* c, const uint32_t* a, uint32_t b0, uint32_t b1) {
    asm volatile("mma.sync.aligned.m16n8k16.row.col.f32.f16.f16.f32 "
                 "{%0,%1,%2,%3}, {%4,%5,%6,%7}, {%8,%9}, {%0,%1,%2,%3};"
                 : "+f"(c[0]), "+f"(c[1]), "+f"(c[2]), "+f"(c[3])
                 : "r"(a[0]), "r"(a[1]), "r"(a[2]), "r"(a[3]), "r"(b0), "r"(b1));
}
__device__ __forceinline__ uint32_t packh2(float lo, float hi) {
    uint32_t r;
    asm("cvt.rn.f16x2.f32 %0, %1, %2;" : "=r"(r) : "f"(hi), "f"(lo));
    return r;
}
__device__ __forceinline__ uint32_t hmax2(uint32_t a, uint32_t b) {
    uint32_t r;
    asm("max.f16x2 %0, %1, %2;" : "=r"(r) : "r"(a), "r"(b));
    return r;
}
__device__ __forceinline__ uint32_t hsub2(uint32_t a, uint32_t b) {
    uint32_t r;
    asm("sub.rn.f16x2 %0, %1, %2;" : "=r"(r) : "r"(a), "r"(b));
    return r;
}
__device__ __forceinline__ uint32_t ex2h2(uint32_t a) {
    uint32_t r;
    asm("ex2.approx.f16x2 %0, %1;" : "=r"(r) : "r"(a));
    return r;
}

// ---------------------------------------------------------------------------
// Merged fp32->fp16 convert: x (2M float4 chunks) + 4 weights (256K chunks ea)
__global__ void cvt_all(const float* __restrict__ x,
                        const float* __restrict__ wq, const float* __restrict__ wk,
                        const float* __restrict__ wv, const float* __restrict__ wo,
                        __half* __restrict__ xh, __half* __restrict__ wh)
{
    const int i = blockIdx.x * blockDim.x + threadIdx.x;   // 0..3145727
    const float* src;
    uint32_t* dst;
    int off;
    if (i < 2097152) {
        src = x; off = i; dst = (uint32_t*)xh;
    } else {
        const int j = i - 2097152;
        const int r = j >> 18;
        off = j & 262143;
        src = (r == 0) ? wq : (r == 1) ? wk : (r == 2) ? wv : wo;
        dst = (uint32_t*)(wh + ((size_t)r << 20));
    }
    const float4 v = ((const float4*)src)[off];
    dst[2 * off + 0] = packh2(v.x, v.y);
    dst[2 * off + 1] = packh2(v.z, v.w);
}

// ---------------------------------------------------------------------------
// Shared GEMM mainloop: 128x128 tile, 3-stage cp.async, one barrier/stage.
// CHANGE vs R12: first fragment loads issue BEFORE the next-stage cp.async
// block, so LDS latency starts immediately after the barrier.
// ---------------------------------------------------------------------------
#define GS 32768
#define GEMM_SMEM (3 * GS)

struct GemmCtx {
    uint32_t sb;
    int tid, wid, lane, wm, wn;
};

__device__ __forceinline__ void gemm_mainloop(
    const GemmCtx& cx, const __half* __restrict__ A, const __half* __restrict__ W,
    int m0, int n0, float acc[2][8][4])
{
    const int tid = cx.tid, lane = cx.lane, wm = cx.wm, wn = cx.wn;
    const uint32_t sb = cx.sb;

    int goff[4], soff[4];
#pragma unroll
    for (int i = 0; i < 4; i++) {
        const int id = tid + (i << 8), r = id >> 3, c = id & 7;
        goff[i] = r * 1024 + c * 8;
        soff[i] = r * 128 + ((c * 16) ^ ((r & 7) << 4));
    }
    auto load_stage = [&](const __half* ga, const __half* gb, int buf) {
        const uint32_t sA = sb + buf * GS, sB = sA + 16384;
#pragma unroll
        for (int i = 0; i < 4; i++) CP16(sA + soff[i], ga + goff[i]);
#pragma unroll
        for (int i = 0; i < 4; i++) CP16(sB + soff[i], gb + goff[i]);
    };

    const __half* ap = A + (size_t)m0 * 1024;
    const __half* wp = W + (size_t)n0 * 1024;
    load_stage(ap, wp, 0); CP_COMMIT(); ap += 64; wp += 64;
    load_stage(ap, wp, 1); CP_COMMIT(); ap += 64; wp += 64;

    const int la15 = lane & 15;
    const int lbr  = ((lane >> 4) << 3) + (lane & 7);
    const uint32_t axy = (uint32_t)(((lane >> 4) << 4) ^ ((la15 & 7) << 4));
    const uint32_t bxy = (uint32_t)((((lane >> 3) & 1) << 4) ^ ((lbr & 7) << 4));
    const int aoff0 = (wm + la15) * 128, aoff1 = (wm + 16 + la15) * 128;
    const int boff  = (wn + lbr) * 128;

    int cbuf = 0, lbuf = 2;
    for (int s = 0; s < 16; s++) {
        if (s < 15) CP_WAIT1(); else CP_WAIT0();
        __syncthreads();

        const uint32_t sA = sb + cbuf * GS, sB = sA + 16384;
        auto ldA = [&](uint32_t a[2][4], int kd) {
            const uint32_t kk = (uint32_t)(kd * 32) ^ axy;
            ldsm4(a[0], sA + aoff0 + kk);
            ldsm4(a[1], sA + aoff1 + kk);
        };
        auto ldB = [&](uint32_t b[4], int kd, int nt2) {
            ldsm4(b, sB + boff + nt2 * 2048 + ((uint32_t)(kd * 32) ^ bxy));
        };

        uint32_t a[2][2][4], b[2][4];
        // fragments first: their LDS latency runs under the cp.async issue
        ldA(a[0], 0);
        ldB(b[0], 0, 0);
        if (s + 2 < 16) { load_stage(ap, wp, lbuf); CP_COMMIT(); ap += 64; wp += 64; }

#pragma unroll
        for (int step = 0; step < 16; step++) {
            const int kd = step >> 2, nt2 = step & 3;
            const int cb = step & 1, ab = kd & 1;
            if (step < 15) ldB(b[cb ^ 1], (step + 1) >> 2, (step + 1) & 3);
            if (nt2 == 1 && kd < 3) ldA(a[ab ^ 1], kd + 1);
#pragma unroll
            for (int mt = 0; mt < 2; mt++) {
                mma16816(acc[mt][nt2 * 2 + 0], a[ab][mt], b[cb][0], b[cb][1]);
                mma16816(acc[mt][nt2 * 2 + 1], a[ab][mt], b[cb][2], b[cb][3]);
            }
        }
        cbuf = (cbuf == 2) ? 0 : cbuf + 1;
        lbuf = (lbuf == 2) ? 0 : lbuf + 1;
    }
}

// Merged Q/K/V projection: grid.z selects weight/bias/output. fp16 head layout.
__global__ void __launch_bounds__(256, 2)
gemm_qkv(const __half* __restrict__ A, const __half* __restrict__ Wbase,
         const float* __restrict__ bq, const float* __restrict__ bk,
         const float* __restrict__ bv,
         __half* __restrict__ Cq, __half* __restrict__ Ck, __half* __restrict__ Cv)
{
    cudaGridDependencySynchronize();               // PDL: wait for cvt_all
    extern __shared__ char smem[];
    GemmCtx cx;
    cx.sb = smem_u32(smem);
    cx.tid = threadIdx.x; cx.wid = cx.tid >> 5; cx.lane = cx.tid & 31;
    cx.wm = (cx.wid & 3) << 5; cx.wn = (cx.wid >> 2) << 6;
    const int m0 = blockIdx.y << 7, n0 = blockIdx.x << 7;
    const int z = blockIdx.z;
    const __half* W = Wbase + ((size_t)z << 20);
    const float* bias = (z == 0) ? bq : (z == 1) ? bk : bv;
    __half* C = (z == 0) ? Cq : (z == 1) ? Ck : Cv;
    const float scale = (z == 0) ? CEXP : 1.0f;

    float acc[2][8][4];
#pragma unroll
    for (int mt = 0; mt < 2; mt++)
#pragma unroll
        for (int nt = 0; nt < 8; nt++)
#pragma unroll
            for (int c = 0; c < 4; c++) acc[mt][nt][c] = 0.f;

    gemm_mainloop(cx, A, W, m0, n0, acc);

    const int r0 = cx.lane >> 2, colq = (cx.lane & 3) * 2;
#pragma unroll
    for (int mt = 0; mt < 2; mt++) {
        const int row0 = m0 + cx.wm + mt * 16 + r0;
#pragma unroll
        for (int nt = 0; nt < 8; nt++) {
            const int col = n0 + cx.wn + nt * 8 + colq;
            const float2 bvv = *(const float2*)(bias + col);
            const float v0 = (acc[mt][nt][0] + bvv.x) * scale;
            const float v1 = (acc[mt][nt][1] + bvv.y) * scale;
            const float v2 = (acc[mt][nt][2] + bvv.x) * scale;
            const float v3 = (acc[mt][nt][3] + bvv.y) * scale;
            const int b = row0 >> 11, h = col >> 6, d = col & 63;
            const size_t hb = (size_t)(((b << 4) + h) << 11);
            *(uint32_t*)(C + (hb + (row0 & 2047)) * 64 + d)       = packh2(v0, v1);
            *(uint32_t*)(C + (hb + ((row0 + 8) & 2047)) * 64 + d) = packh2(v2, v3);
        }
    }
}

// Output projection: fp32 row-major out.
__global__ void __launch_bounds__(256, 2)
gemm_o(const __half* __restrict__ A, const __half* __restrict__ W,
       const float* __restrict__ bias, float* __restrict__ C)
{
    cudaGridDependencySynchronize();               // PDL: wait for flash_hmma
    extern __shared__ char smem[];
    GemmCtx cx;
    cx.sb = smem_u32(smem);
    cx.tid = threadIdx.x; cx.wid = cx.tid >> 5; cx.lane = cx.tid & 31;
    cx.wm = (cx.wid & 3) << 5; cx.wn = (cx.wid >> 2) << 6;
    const int m0 = blockIdx.y << 7, n0 = blockIdx.x << 7;

    float acc[2][8][4];
#pragma unroll
    for (int mt = 0; mt < 2; mt++)
#pragma unroll
        for (int nt = 0; nt < 8; nt++)
#pragma unroll
            for (int c = 0; c < 4; c++) acc[mt][nt][c] = 0.f;

    gemm_mainloop(cx, A, W, m0, n0, acc);

    const int r0 = cx.lane >> 2, colq = (cx.lane & 3) * 2;
#pragma unroll
    for (int mt = 0; mt < 2; mt++) {
        const int row0 = m0 + cx.wm + mt * 16 + r0;
#pragma unroll
        for (int nt = 0; nt < 8; nt++) {
            const int col = n0 + cx.wn + nt * 8 + colq;
            const float2 bvv = *(const float2*)(bias + col);
            *(float2*)(C + (size_t)row0 * 1024 + col) =
                make_float2(acc[mt][nt][0] + bvv.x, acc[mt][nt][1] + bvv.y);
            *(float2*)(C + (size_t)(row0 + 8) * 1024 + col) =
                make_float2(acc[mt][nt][2] + bvv.x, acc[mt][nt][3] + bvv.y);
        }
    }
}

// ---------------------------------------------------------------------------
// Flash attention (R12 math): fp16 HMMA, 64-key subtiles, 4-stage ring, one
// barrier per PAIR. CHANGE: next-pair cp.async issue moved BETWEEN the two
// attn tiles so tile-0's fragment loads start right after the barrier.
// ---------------------------------------------------------------------------
#define FS 16384                     // bytes per KV stage (K 8K + V 8K), 64 keys
#define FLASH_SMEM (16384 + 4 * FS)  // Q 16K + 4 stages = 80K

__global__ void __launch_bounds__(256, 2)
flash_hmma(const __half* __restrict__ Q, const __half* __restrict__ K,
           const __half* __restrict__ V, __half* __restrict__ O)
{
    cudaGridDependencySynchronize();               // PDL: wait for gemm_qkv
    extern __shared__ char smem[];
    const uint32_t sb = smem_u32(smem);
    const uint32_t sQ = sb, sKV = sb + 16384;       // 4 stages of [K 8K | V 8K]
    const int tid = threadIdx.x, wid = tid >> 5, lane = tid & 31;
    const int q0 = blockIdx.x << 7, bh = blockIdx.y;
    const size_t base = (size_t)bh * (2048 * 64);
    const __half* Qb = Q + base + (size_t)q0 * 64;
    const uint32_t ONES = 0x3C003C00u;

    int g0, g1, s0, s1;
    {
        const int r0_ = tid >> 3, c_ = tid & 7;
        const int r1_ = (tid + 256) >> 3;
        g0 = r0_ * 64 + c_ * 8;  s0 = r0_ * 128 + ((c_ * 16) ^ ((r0_ & 7) << 4));
        g1 = r1_ * 64 + c_ * 8;  s1 = r1_ * 128 + ((c_ * 16) ^ ((r1_ & 7) << 4));
    }

#pragma unroll
    for (int i = 0; i < 4; i++) {                   // Q tile: 128 x 64 halves
        const int id = tid + (i << 8), r = id >> 3, c = id & 7;
        CP16(sQ + r * 128 + ((c * 16) ^ ((r & 7) << 4)), Qb + (size_t)r * 64 + c * 8);
    }
    auto load_kv = [&](const __half* kp, const __half* vp, int buf) {
        const uint32_t ks_ = sKV + buf * FS, vs_ = ks_ + 8192;
        CP16(ks_ + s0, kp + g0);
        CP16(ks_ + s1, kp + g1);
        CP16(vs_ + s0, vp + g0);
        CP16(vs_ + s1, vp + g1);
    };
    const __half* kp = K + base;
    const __half* vp = V + base;
    load_kv(kp, vp, 0); CP_COMMIT();                // g0 incl Q
    load_kv(kp + 4096, vp + 4096, 1); CP_COMMIT();
    kp += 8192; vp += 8192;
    CP_WAIT0();
    __syncthreads();

    uint32_t qf[4][4];
#pragma unroll
    for (int kd = 0; kd < 4; kd++) {
        const int r = (wid << 4) + (lane & 15);
        const int cb = kd * 32 + ((lane >> 4) << 4);
        ldsm4(qf[kd], sQ + r * 128 + (cb ^ ((r & 7) << 4)));
    }

    const int klr  = ((lane >> 4) << 3) + (lane & 7);
    const int koff = klr * 128;
    const uint32_t kxy = (uint32_t)((((lane >> 3) & 1) << 4) ^ ((klr & 7) << 4));
    const int voff = (lane & 15) * 128;
    const uint32_t vxy = (uint32_t)(((lane >> 4) << 4) ^ ((lane & 7) << 4));

    float oacc[8][4];
#pragma unroll
    for (int dn = 0; dn < 8; dn++)
#pragma unroll
        for (int c = 0; c < 4; c++) oacc[dn][c] = 0.f;
    uint32_t mrp = 0xFC00FC00u;                     // (-inf, -inf) running max
    float l0 = 0.f, l1 = 0.f;

    auto attn_tile = [&](uint32_t ks_, uint32_t vs_) {
        float sacc[8][4];
#pragma unroll
        for (int nt = 0; nt < 8; nt++)
#pragma unroll
            for (int c = 0; c < 4; c++) sacc[nt][c] = 0.f;
        {
            uint32_t b[2][4];
            auto ldK = [&](uint32_t* bb, int step) {
                const int kd = step >> 2, nt2 = step & 3;
                ldsm4(bb, ks_ + koff + nt2 * 2048 + ((uint32_t)(kd * 32) ^ kxy));
            };
            ldK(b[0], 0);
#pragma unroll
            for (int step = 0; step < 16; step++) {
                const int nt2 = step & 3, cb = step & 1, kd = step >> 2;
                if (step < 15) ldK(b[cb ^ 1], step + 1);
                mma16816(sacc[nt2 * 2 + 0], qf[kd], b[cb][0], b[cb][1]);
                mma16816(sacc[nt2 * 2 + 1], qf[kd], b[cb][2], b[cb][3]);
            }
        }

        // --- f16x2 softmax ---
#pragma unroll
        for (int nt = 0; nt < 8; nt++) {
            sacc[nt][0] = __uint_as_float(packh2(sacc[nt][0], sacc[nt][1]));
            sacc[nt][2] = __uint_as_float(packh2(sacc[nt][2], sacc[nt][3]));
        }
        // prefetch first V fragments: LDSM latency hides under softmax chain
        uint32_t vb[2][4];
        ldsm4t(vb[0], vs_ + voff + (0 ^ vxy));
        // packed per-thread max trees
        uint32_t t0 = hmax2(__float_as_uint(sacc[0][0]), __float_as_uint(sacc[1][0]));
        uint32_t t1 = hmax2(__float_as_uint(sacc[2][0]), __float_as_uint(sacc[3][0]));
        uint32_t t2 = hmax2(__float_as_uint(sacc[4][0]), __float_as_uint(sacc[5][0]));
        uint32_t t3 = hmax2(__float_as_uint(sacc[6][0]), __float_as_uint(sacc[7][0]));
        uint32_t m0 = hmax2(hmax2(t0, t1), hmax2(t2, t3));
        t0 = hmax2(__float_as_uint(sacc[0][2]), __float_as_uint(sacc[1][2]));
        t1 = hmax2(__float_as_uint(sacc[2][2]), __float_as_uint(sacc[3][2]));
        t2 = hmax2(__float_as_uint(sacc[4][2]), __float_as_uint(sacc[5][2]));
        t3 = hmax2(__float_as_uint(sacc[6][2]), __float_as_uint(sacc[7][2]));
        uint32_t m1 = hmax2(hmax2(t0, t1), hmax2(t2, t3));
        m0 = hmax2(m0, __byte_perm(m0, 0, 0x1032));
        m1 = hmax2(m1, __byte_perm(m1, 0, 0x1032));
        uint32_t mp = __byte_perm(m0, m1, 0x7610);    // (row0max, row1max)
        mp = hmax2(mp, __shfl_xor_sync(0xffffffffu, mp, 1));
        mp = hmax2(mp, __shfl_xor_sync(0xffffffffu, mp, 2));
        const uint32_t mold = mrp;
        const uint32_t mn = hmax2(mold, mp);
        mrp = mn;
        const uint32_t alp = ex2h2(hsub2(mold, mn));
        const float2 alf = __half22float2(*(const __half2*)&alp);
        if (!__all_sync(0xffffffffu, mn == mold)) {
#pragma unroll
            for (int dn = 0; dn < 8; dn++) {
                oacc[dn][0] *= alf.x; oacc[dn][1] *= alf.x;
                oacc[dn][2] *= alf.y; oacc[dn][3] *= alf.y;
            }
        }
        const uint32_t mn0 = __byte_perm(mn, 0, 0x1010);
        const uint32_t mn1 = __byte_perm(mn, 0, 0x3232);
#pragma unroll
        for (int nt = 0; nt < 8; nt++) {
            sacc[nt][0] = __uint_as_float(ex2h2(hsub2(__float_as_uint(sacc[nt][0]), mn0)));
            sacc[nt][2] = __uint_as_float(ex2h2(hsub2(__float_as_uint(sacc[nt][2]), mn1)));
        }

        // O += P V; row sums via ones-B HMMA, two alternating accumulators
        float rsa[4] = {0.f, 0.f, 0.f, 0.f};
        float rsb[4] = {0.f, 0.f, 0.f, 0.f};
        {
            uint32_t a[4];
            auto ldVt = [&](uint32_t* bb, int step) {
                const int ks = step >> 2, dn2 = step & 3;
                ldsm4t(bb, vs_ + voff + ks * 2048 + ((uint32_t)(dn2 * 32) ^ vxy));
            };
#pragma unroll
            for (int step = 0; step < 16; step++) {
                const int ks = step >> 2, dn2 = step & 3, cb = step & 1;
                if (step < 15) ldVt(vb[cb ^ 1], step + 1);
                if (dn2 == 0) {
                    a[0] = __float_as_uint(sacc[2 * ks][0]);
                    a[1] = __float_as_uint(sacc[2 * ks][2]);
                    a[2] = __float_as_uint(sacc[2 * ks + 1][0]);
                    a[3] = __float_as_uint(sacc[2 * ks + 1][2]);
                    mma16816((ks & 1) ? rsb : rsa, a, ONES, ONES);
                }
                mma16816(oacc[dn2 * 2 + 0], a, vb[cb][0], vb[cb][1]);
                mma16816(oacc[dn2 * 2 + 1], a, vb[cb][2], vb[cb][3]);
            }
        }
        l0 = l0 * alf.x + (rsa[0] + rsb[0]);
        l1 = l1 * alf.y + (rsa[2] + rsb[2]);
    };

    // main loop: 16 pairs; next-pair loads issued BETWEEN the two tiles so
    // tile-0's ldK starts immediately after the barrier.
    for (int p = 0; p < 16; p++) {
        if (p > 0) {
            CP_WAIT0();
            __syncthreads();
        }
        const uint32_t b0 = sKV + ((2 * p) & 3) * FS;
        const uint32_t b1 = sKV + ((2 * p + 1) & 3) * FS;
        attn_tile(b0, b0 + 8192);
        if (p < 15) {
            load_kv(kp, vp, (2 * p + 2) & 3); CP_COMMIT();
            load_kv(kp + 4096, vp + 4096, (2 * p + 3) & 3); CP_COMMIT();
            kp += 8192; vp += 8192;
        }
        attn_tile(b1, b1 + 8192);
    }

    // normalize + write packed [b][s][h*64+d] fp16
    const int b_ = bh >> 4, h_ = bh & 15;
    __half* Ob = O + ((size_t)b_ * 2048 + q0) * 1024 + h_ * 64;
    const float inv0 = 1.f / l0, inv1 = 1.f / l1;
    const int r0 = (wid << 4) + (lane >> 2), colq = (lane & 3) * 2;
#pragma unroll
    for (int dn = 0; dn < 8; dn++) {
        const int col = dn * 8 + colq;
        *(uint32_t*)(Ob + (size_t)r0 * 1024 + col) =
            packh2(oacc[dn][0] * inv0, oacc[dn][1] * inv0);
        *(uint32_t*)(Ob + (size_t)(r0 + 8) * 1024 + col) =
            packh2(oacc[dn][2] * inv1, oacc[dn][3] * inv1);
    }
}

// ---------------------------------------------------------------------------
extern "C" void kernel_launch(void* const* d_in, const int* in_sizes, int n_in,
                              void* d_out, int out_size)
{
    const float* x  = (const float*)d_in[0];
    const float* wq = (const float*)d_in[1];
    const float* bq = (const float*)d_in[2];
    const float* wk = (const float*)d_in[3];
    const float* bk = (const float*)d_in[4];
    const float* wv = (const float*)d_in[5];
    const float* bv = (const float*)d_in[6];
    const float* wo = (const float*)d_in[7];
    const float* bo = (const float*)d_in[8];
    float* out = (float*)d_out;

    __half *xh, *wh, *qh, *kh, *vh, *aoh;
    cudaGetSymbolAddress((void**)&xh,  g_xh);
    cudaGetSymbolAddress((void**)&wh,  g_wh);
    cudaGetSymbolAddress((void**)&qh,  g_qh);
    cudaGetSymbolAddress((void**)&kh,  g_kh);
    cudaGetSymbolAddress((void**)&vh,  g_vh);
    cudaGetSymbolAddress((void**)&aoh, g_aoh);

    cudaFuncSetAttribute(gemm_qkv, cudaFuncAttributeMaxDynamicSharedMemorySize, GEMM_SMEM);
    cudaFuncSetAttribute(gemm_o,   cudaFuncAttributeMaxDynamicSharedMemorySize, GEMM_SMEM);
    cudaFuncSetAttribute(flash_hmma, cudaFuncAttributeMaxDynamicSharedMemorySize, FLASH_SMEM);

    cvt_all<<<12288, 256>>>(x, wq, wk, wv, wo, xh, wh);

    cudaLaunchAttribute at[1];
    at[0].id = cudaLaunchAttributeProgrammaticStreamSerialization;
    at[0].val.programmaticStreamSerializationAllowed = 1;

    {
        cudaLaunchConfig_t cfg = {};
        cfg.gridDim = dim3(8, 64, 3);
        cfg.blockDim = dim3(256, 1, 1);
        cfg.dynamicSmemBytes = GEMM_SMEM;
        cfg.stream = 0;
        cfg.attrs = at; cfg.numAttrs = 1;
        cudaLaunchKernelEx(&cfg, gemm_qkv, (const __half*)xh, (const __half*)wh,
                           bq, bk, bv, qh, kh, vh);
    }
    {
        cudaLaunchConfig_t cfg = {};
        cfg.gridDim = dim3(16, 64, 1);
        cfg.blockDim = dim3(256, 1, 1);
        cfg.dynamicSmemBytes = FLASH_SMEM;
        cfg.stream = 0;
        cfg.attrs = at; cfg.numAttrs = 1;
        cudaLaunchKernelEx(&cfg, flash_hmma, (const __half*)qh, (const __half*)kh,
                           (const __half*)vh, aoh);
    }
    {
        cudaLaunchConfig_t cfg = {};
        cfg.gridDim = dim3(8, 64, 1);
        cfg.blockDim = dim3(256, 1, 1);
        cfg.dynamicSmemBytes = GEMM_SMEM;
        cfg.stream = 0;
        cfg.attrs = at; cfg.numAttrs = 1;
        cudaLaunchKernelEx(&cfg, gemm_o, (const __half*)aoh,
                           (const __half*)(wh + 3145728), bo, out);
    }
}